// round 15
// baseline (speedup 1.0000x reference)
#include <cuda_runtime.h>
#include <cuda_bf16.h>
#include <cstdint>

#define BATCH 4
#define NTOK  4096
#define CIN   128
#define FDIM  256
#define MTOT  (BATCH*NTOK)   // 16384

// ---------------- scratch (device globals) -----------------------------------
__device__ float          g_x  [MTOT*FDIM];   // fp32 x for residual
__device__ __nv_bfloat16  g_ib [MTOT*CIN];    // bf16 hi(inputs)
__device__ __nv_bfloat16  g_ibl[MTOT*CIN];    // bf16 lo(inputs)
__device__ __nv_bfloat16  g_wc [CIN*3*FDIM];  // folded weights [128][768]
__device__ float          g_bc [3*FDIM];      // folded biases
__device__ __nv_bfloat16  g_wph[CIN*FDIM];    // hi(W_proj)
__device__ __nv_bfloat16  g_wpl[CIN*FDIM];    // lo(W_proj)
__device__ unsigned char  g_q8 [MTOT*FDIM];   // Q in e4m3, scaled x8
__device__ unsigned char  g_k8 [MTOT*FDIM];   // K in e4m3, scaled x8
// V e4m3 x8, transposed tile-major: [batch][ktile=64][d=256][key_in_tile=64]
__device__ unsigned char  g_v8t[MTOT*FDIM];

// ---------------- helpers ------------------------------------------------------
static __device__ __forceinline__ uint32_t smem_u32(const void* p) {
    return (uint32_t)__cvta_generic_to_shared(p);
}
static __device__ __forceinline__ void ldmx4(uint32_t& r0, uint32_t& r1,
                                             uint32_t& r2, uint32_t& r3, uint32_t addr) {
    asm volatile("ldmatrix.sync.aligned.m8n8.x4.shared.b16 {%0,%1,%2,%3}, [%4];"
                 : "=r"(r0), "=r"(r1), "=r"(r2), "=r"(r3) : "r"(addr));
}
static __device__ __forceinline__ void ldmx4t(uint32_t& r0, uint32_t& r1,
                                              uint32_t& r2, uint32_t& r3, uint32_t addr) {
    asm volatile("ldmatrix.sync.aligned.m8n8.x4.trans.shared.b16 {%0,%1,%2,%3}, [%4];"
                 : "=r"(r0), "=r"(r1), "=r"(r2), "=r"(r3) : "r"(addr));
}
static __device__ __forceinline__ void mma_bf16(float* c, const uint32_t* a,
                                                uint32_t b0, uint32_t b1) {
    asm volatile("mma.sync.aligned.m16n8k16.row.col.f32.bf16.bf16.f32 "
                 "{%0,%1,%2,%3}, {%4,%5,%6,%7}, {%8,%9}, {%0,%1,%2,%3};"
                 : "+f"(c[0]), "+f"(c[1]), "+f"(c[2]), "+f"(c[3])
                 : "r"(a[0]), "r"(a[1]), "r"(a[2]), "r"(a[3]), "r"(b0), "r"(b1));
}
static __device__ __forceinline__ void mma_fp8(float* c, const uint32_t* a,
                                               uint32_t b0, uint32_t b1) {
    asm volatile("mma.sync.aligned.m16n8k32.row.col.f32.e4m3.e4m3.f32 "
                 "{%0,%1,%2,%3}, {%4,%5,%6,%7}, {%8,%9}, {%0,%1,%2,%3};"
                 : "+f"(c[0]), "+f"(c[1]), "+f"(c[2]), "+f"(c[3])
                 : "r"(a[0]), "r"(a[1]), "r"(a[2]), "r"(a[3]), "r"(b0), "r"(b1));
}
static __device__ __forceinline__ unsigned short pack_e4m3x2(float lo, float hi) {
    unsigned short d;
    asm("cvt.rn.satfinite.e4m3x2.f32 %0, %1, %2;" : "=h"(d) : "f"(hi), "f"(lo));
    return d;
}
static __device__ __forceinline__ void sts16(uint32_t addr, unsigned short v) {
    asm volatile("st.shared.b16 [%0], %1;" :: "r"(addr), "h"(v));
}
static __device__ __forceinline__ void cp16(uint32_t s, const void* g) {
    asm volatile("cp.async.cg.shared.global [%0], [%1], 16;" :: "r"(s), "l"(g));
}
static __device__ __forceinline__ void cp_commit() {
    asm volatile("cp.async.commit_group;");
}
template<int N> static __device__ __forceinline__ void cp_wait() {
    asm volatile("cp.async.wait_group %0;" :: "n"(N));
}

// ---------------- kernel 0: prep = conv(hi+lo) + fold + bias_fold ---------------
__global__ void __launch_bounds__(256) prep_kernel(const float* __restrict__ in,
                                                   const float* __restrict__ Wp,
                                                   const float* __restrict__ bp,
                                                   const float* __restrict__ Wq,
                                                   const float* __restrict__ bq,
                                                   const float* __restrict__ Wk,
                                                   const float* __restrict__ bk,
                                                   const float* __restrict__ Wv,
                                                   const float* __restrict__ bv) {
    __shared__ float sWj[64][65];
    __shared__ float sWp[64][36];
    const int bx = blockIdx.x, tid = threadIdx.x;

    if (bx < 2048) {                       // ---- conv: fp32 -> bf16 hi + lo ----
        int i = bx * 256 + tid;
        float4 v = ((const float4*)in)[i];
        __nv_bfloat16 hx = __float2bfloat16(v.x);
        __nv_bfloat16 hy = __float2bfloat16(v.y);
        __nv_bfloat16 hz = __float2bfloat16(v.z);
        __nv_bfloat16 hw = __float2bfloat16(v.w);
        ((__nv_bfloat162*)g_ib)[2 * i]     = __nv_bfloat162(hx, hy);
        ((__nv_bfloat162*)g_ib)[2 * i + 1] = __nv_bfloat162(hz, hw);
        ((__nv_bfloat162*)g_ibl)[2 * i] = __floats2bfloat162_rn(
            v.x - __bfloat162float(hx), v.y - __bfloat162float(hy));
        ((__nv_bfloat162*)g_ibl)[2 * i + 1] = __floats2bfloat162_rn(
            v.z - __bfloat162float(hz), v.w - __bfloat162float(hw));
        return;
    }
    if (bx < 2096) {                       // ---- fold Wc = Wp @ W{q,k,v} ----
        const int f = bx - 2048;
        const int j = f >> 4;
        const int g0 = ((f >> 2) & 3) * 64, c0 = (f & 3) * 32;
        const float* Wj = (j == 0) ? Wq : ((j == 1) ? Wk : Wv);
        const int tg = tid & 63, tc = tid >> 6;
        float acc[8];
#pragma unroll
        for (int i = 0; i < 8; i++) acc[i] = 0.f;

        for (int f0 = 0; f0 < 256; f0 += 64) {
#pragma unroll
            for (int i = tid; i < 4096; i += 256)
                sWj[i >> 6][i & 63] = Wj[(size_t)(f0 + (i >> 6)) * 256 + g0 + (i & 63)];
#pragma unroll
            for (int i = tid; i < 2048; i += 256)
                sWp[i & 63][i >> 6] = Wp[(size_t)(c0 + (i >> 6)) * 256 + f0 + (i & 63)];
            __syncthreads();
#pragma unroll 16
            for (int ff = 0; ff < 64; ff++) {
                float wj = sWj[ff][tg];
                float4 p0 = *(const float4*)&sWp[ff][tc * 8];
                float4 p1 = *(const float4*)&sWp[ff][tc * 8 + 4];
                acc[0] += p0.x * wj; acc[1] += p0.y * wj;
                acc[2] += p0.z * wj; acc[3] += p0.w * wj;
                acc[4] += p1.x * wj; acc[5] += p1.y * wj;
                acc[6] += p1.z * wj; acc[7] += p1.w * wj;
            }
            __syncthreads();
        }
#pragma unroll
        for (int i = 0; i < 8; i++)
            g_wc[(size_t)(c0 + tc * 8 + i) * 768 + j * 256 + g0 + tg] =
                __float2bfloat16(acc[i]);
        return;
    }
    {                                      // ---- bias fold ----
        const int j = bx - 2096, g = tid;
        const float* Wj = (j == 0) ? Wq : ((j == 1) ? Wk : Wv);
        const float* bj = (j == 0) ? bq : ((j == 1) ? bk : bv);
        float acc = bj[g];
        for (int f = 0; f < 256; f++) acc += bp[f] * Wj[(size_t)f * 256 + g];
        g_bc[j * 256 + g] = acc;
    }
}

// ---------------- kernel 0b: split W_proj into hi/lo bf16 -----------------------
__global__ void __launch_bounds__(256) wsplit_kernel(const float* __restrict__ Wp) {
    int i = blockIdx.x * 256 + threadIdx.x;   // 32768 elems, grid 128
    float w = Wp[i];
    __nv_bfloat16 h = __float2bfloat16(w);
    g_wph[i] = h;
    g_wpl[i] = __float2bfloat16(w - __bfloat162float(h));
}

// ---------------- kernel 2: Q/K/V (fp8) + x (split-bf16 fp32), BM=128 -----------
// Grid (128, 16), 256 threads (8 warps x 16 rows). y<12: q/k/v. y>=12: x-path.
__global__ void __launch_bounds__(256) qkv_kernel(const float* __restrict__ bp) {
    __shared__ __align__(16) __nv_bfloat16 sA[128][72];   // 18 KB
    __shared__ __align__(16) __nv_bfloat16 sW[64][72];    // 9 KB
    __shared__ __align__(16) unsigned char sT[64 * 144];  // V transpose staging (9 KB)
    const int m0 = blockIdx.x * 128;
    const int tid = threadIdx.x, warp = tid >> 5, lane = tid & 31;

    float o[8][4];
#pragma unroll
    for (int jj = 0; jj < 8; jj++)
#pragma unroll
        for (int r = 0; r < 4; r++) o[jj][r] = 0.f;

    const uint32_t a_addr0 = smem_u32(&sA[warp * 16 + (lane & 15)][(lane & 16) >> 1]);
    const uint32_t b_addr0 = smem_u32(&sW[(lane & 7) + (lane & 8)][(lane & 16) >> 1]);
    const int g = lane >> 2, qd = lane & 3;

    if (blockIdx.y < 12) {
        // ---------------- q/k/v path ----------------
        const int j = blockIdx.y >> 2, g0 = (blockIdx.y & 3) * 64;

        for (int k0 = 0; k0 < CIN; k0 += 64) {
            __syncthreads();
#pragma unroll
            for (int i = tid; i < 1024; i += 256) {     // A: 128x64 bf16
                int r = i >> 3, c8 = i & 7;
                *(uint4*)&sA[r][c8 * 8] =
                    *(const uint4*)&g_ib[(size_t)(m0 + r) * CIN + k0 + c8 * 8];
            }
#pragma unroll
            for (int i = tid; i < 512; i += 256) {      // W: 64x64 bf16
                int r = i >> 3, c8 = i & 7;
                *(uint4*)&sW[r][c8 * 8] =
                    *(const uint4*)&g_wc[(size_t)(k0 + r) * 768 + j * 256 + g0 + c8 * 8];
            }
            __syncthreads();
#pragma unroll
            for (int kc = 0; kc < 4; kc++) {
                uint32_t a[4];
                ldmx4(a[0], a[1], a[2], a[3], a_addr0 + kc * 16 * 2);
#pragma unroll
                for (int np = 0; np < 4; np++) {
                    uint32_t b0, b1, b2, b3;
                    ldmx4t(b0, b1, b2, b3,
                           b_addr0 + (uint32_t)(kc * 16 * 72 + np * 16) * 2);
                    mma_bf16(o[2 * np],     a, b0, b1);
                    mma_bf16(o[2 * np + 1], a, b2, b3);
                }
            }
        }
        const int row = m0 + warp * 16 + g;
        if (j < 2) {
            unsigned char* out8 = (j == 0) ? g_q8 : g_k8;
#pragma unroll
            for (int jj = 0; jj < 8; jj++) {
                int col = g0 + jj * 8 + qd * 2;
                float bf0 = g_bc[j * 256 + col], bf1 = g_bc[j * 256 + col + 1];
                *(unsigned short*)&out8[(size_t)row * FDIM + col] =
                    pack_e4m3x2((o[jj][0] + bf0) * 8.f, (o[jj][1] + bf1) * 8.f);
                *(unsigned short*)&out8[(size_t)(row + 8) * FDIM + col] =
                    pack_e4m3x2((o[jj][2] + bf0) * 8.f, (o[jj][3] + bf1) * 8.f);
            }
        } else {
            // V: transpose to [d][token(128)] in smem (e4m3 x8), 2 ktiles/block
            const int batch = m0 >> 12;
            const int kt0 = (m0 & 4095) >> 6;          // first of 2 tiles
            const int t0 = warp * 16 + g, t1 = t0 + 8; // token-in-block 0..127
#pragma unroll
            for (int jj = 0; jj < 8; jj++) {
                int c = jj * 8 + qd * 2;  // local d index 0..63
                float bf0 = g_bc[512 + g0 + c], bf1 = g_bc[512 + g0 + c + 1];
                sT[c * 144 + t0]       = (unsigned char)pack_e4m3x2((o[jj][0] + bf0) * 8.f, 0.f);
                sT[(c + 1) * 144 + t0] = (unsigned char)pack_e4m3x2((o[jj][1] + bf1) * 8.f, 0.f);
                sT[c * 144 + t1]       = (unsigned char)pack_e4m3x2((o[jj][2] + bf0) * 8.f, 0.f);
                sT[(c + 1) * 144 + t1] = (unsigned char)pack_e4m3x2((o[jj][3] + bf1) * 8.f, 0.f);
            }
            __syncthreads();
            if (tid < 128) {
                const int til = tid >> 6, c = tid & 63;
                unsigned char* dst =
                    g_v8t + (((size_t)(batch * 64 + kt0 + til) * 256) + g0 + c) * 64;
                const uint4* src = (const uint4*)&sT[c * 144 + til * 64];
                ((uint4*)dst)[0] = src[0];
                ((uint4*)dst)[1] = src[1];
                ((uint4*)dst)[2] = src[2];
                ((uint4*)dst)[3] = src[3];
            }
        }
    } else {
        // ---------------- x-path: x = hi@Whi + hi@Wlo + lo@Whi + bp ----------------
        const int g0 = (blockIdx.y - 12) * 64;

#pragma unroll 1
        for (int c = 0; c < 6; c++) {
            const int pass = c >> 1, ksub = (c & 1) * 64;
            const __nv_bfloat16* Asrc = (pass == 2) ? g_ibl : g_ib;
            const __nv_bfloat16* Wsrc = (pass == 1) ? g_wpl : g_wph;
            __syncthreads();
#pragma unroll
            for (int i = tid; i < 1024; i += 256) {
                int r = i >> 3, c8 = i & 7;
                *(uint4*)&sA[r][c8 * 8] =
                    *(const uint4*)&Asrc[(size_t)(m0 + r) * CIN + ksub + c8 * 8];
            }
#pragma unroll
            for (int i = tid; i < 512; i += 256) {
                int r = i >> 3, c8 = i & 7;
                *(uint4*)&sW[r][c8 * 8] =
                    *(const uint4*)&Wsrc[(size_t)(ksub + r) * FDIM + g0 + c8 * 8];
            }
            __syncthreads();
#pragma unroll
            for (int kc = 0; kc < 4; kc++) {
                uint32_t a[4];
                ldmx4(a[0], a[1], a[2], a[3], a_addr0 + kc * 16 * 2);
#pragma unroll
                for (int np = 0; np < 4; np++) {
                    uint32_t b0, b1, b2, b3;
                    ldmx4t(b0, b1, b2, b3,
                           b_addr0 + (uint32_t)(kc * 16 * 72 + np * 16) * 2);
                    mma_bf16(o[2 * np],     a, b0, b1);
                    mma_bf16(o[2 * np + 1], a, b2, b3);
                }
            }
        }
        const int row = m0 + warp * 16 + g;
#pragma unroll
        for (int jj = 0; jj < 8; jj++) {
            int col = g0 + jj * 8 + qd * 2;
            float b0 = bp[col], b1 = bp[col + 1];
            float2 v0 = make_float2(o[jj][0] + b0, o[jj][1] + b1);
            float2 v1 = make_float2(o[jj][2] + b0, o[jj][3] + b1);
            *(float2*)&g_x[(size_t)row * FDIM + col] = v0;
            *(float2*)&g_x[(size_t)(row + 8) * FDIM + col] = v1;
        }
    }
}

// ---------------- kernel 3: all-fp8 flash attention (r14 + ALU strips) ----------
// Grid (64,4); 256 threads (8 warps). BM=64, BN=64, D=256, 2 CTAs/SM.
#define QOFF  0
#define KOFF  16384
#define VTOFF 49152
#define VTSZ  20480
#define POFF  90112
#define LOFF  95232
#define ATT_SMEM (LOFF + 512)

__global__ void __launch_bounds__(256, 2) attn_kernel(float* __restrict__ out,
                                                      const float* __restrict__ gamma_p) {
    extern __shared__ char smem[];
    const uint32_t sb = smem_u32(smem);
    const int batch = blockIdx.y, mt = blockIdx.x;
    const int tid = threadIdx.x, w = tid >> 5, lane = tid & 31;
    const int rg = w >> 1;
    const int h  = w & 1;
    const int rlow = (lane & 7) + (lane & 8);
    const int ghi  = (lane >> 4) & 1;
    const int l7   = lane & 7;

    const unsigned char* Qg  = g_q8  + ((size_t)batch * NTOK + mt * 64) * FDIM;
    const unsigned char* Kg  = g_k8  + (size_t)batch * NTOK * FDIM;
    const unsigned char* VTg = g_v8t + (size_t)batch * 64 * 16384;

    // ---- loop-invariant prefetch bases (chunk stride = immediate; swizzle
    //      bits invariant under +256 thread stride) ----
    const int pr = tid >> 4, pg = tid & 15;
    const uint32_t kS0 = (uint32_t)(pr * 256 + ((pg ^ (pr & 7)) << 4));
    const uint32_t kG0 = (uint32_t)(pr * 256 + pg * 16);
    const int pd = tid >> 2, p4 = tid & 3;
    const uint32_t vS0 = (uint32_t)(pd * 80 + p4 * 16);
    const uint32_t vG0 = (uint32_t)(pd * 64 + p4 * 16);

    // ---- prologue: Q, K0, Vt0 in one group ----
#pragma unroll
    for (int c = 0; c < 4; c++) {
        cp16(sb + QOFF + kS0 + c * 4096, Qg + kG0 + c * 4096);
        cp16(sb + KOFF + kS0 + c * 4096, Kg + kG0 + c * 4096);
        cp16(sb + VTOFF + vS0 + c * 5120, VTg + vG0 + c * 4096);
    }
    cp_commit();

    // persistent prefetch pointers (measured win, round 14)
    const unsigned char* Kp = Kg + 16384;
    const unsigned char* Vp = VTg + 16384;

    float o[4][4][4];
#pragma unroll
    for (int mg = 0; mg < 4; mg++)
#pragma unroll
        for (int nt = 0; nt < 4; nt++)
#pragma unroll
            for (int r = 0; r < 4; r++) o[mg][nt][r] = 0.f;
    float l0 = 0.f, l1 = 0.f;

    // swizzle algebra: ((kc*2+ghi)^l7)<<4 == (kc*32) ^ e16, e16=(ghi^l7)<<4
    const uint32_t e16 = (uint32_t)((ghi ^ l7) << 4);
    const uint32_t qbase = sb + QOFF + (rg * 16 + rlow) * 256;
    const int prow0 = rg * 16 + (lane >> 2), prow1 = prow0 + 8;
    const uint32_t pst0 = sb + POFF + prow0 * 80 + h * 32 + (lane & 3) * 2;
    const uint32_t pst1 = sb + POFF + prow1 * 80 + h * 32 + (lane & 3) * 2;
    const uint32_t pldL = (uint32_t)(((l7 + ((lane >> 3) & 1) * 8) * 80) + ghi * 16);
    const uint32_t vldL = (uint32_t)(((l7 + ghi * 8) * 80) + (((lane >> 3) & 1) * 16));

    cp_wait<0>();
    __syncthreads();

    for (int kt = 0; kt < 64; kt++) {
        const int cur = kt & 1;

        if (kt + 1 < 64) {
            const uint32_t kb = sb + KOFF  + (cur ^ 1) * 16384;
            const uint32_t vb = sb + VTOFF + (cur ^ 1) * VTSZ;
            cp16(kb + kS0,         Kp + kG0);
            cp16(kb + kS0 + 4096,  Kp + kG0 + 4096);
            cp16(kb + kS0 + 8192,  Kp + kG0 + 8192);
            cp16(kb + kS0 + 12288, Kp + kG0 + 12288);
            cp16(vb + vS0,         Vp + vG0);
            cp16(vb + vS0 + 5120,  Vp + vG0 + 4096);
            cp16(vb + vS0 + 10240, Vp + vG0 + 8192);
            cp16(vb + vS0 + 15360, Vp + vG0 + 12288);
            cp_commit();
            Kp += 16384;
            Vp += 16384;
        }

        float s[4][4];
#pragma unroll
        for (int jj = 0; jj < 4; jj++)
#pragma unroll
            for (int r = 0; r < 4; r++) s[jj][r] = 0.f;

        const uint32_t kb = sb + KOFF + cur * 16384 + (uint32_t)((h * 32 + rlow) * 256);
#pragma unroll
        for (int kc = 0; kc < 8; kc++) {
            const uint32_t gsw = ((uint32_t)(kc * 32)) ^ e16;
            uint32_t a[4];
            ldmx4(a[0], a[1], a[2], a[3], qbase + gsw);
#pragma unroll
            for (int np2 = 0; np2 < 2; np2++) {
                uint32_t b0, b1, b2, b3;
                ldmx4(b0, b1, b2, b3, kb + (uint32_t)(np2 * 4096) + gsw);
                mma_fp8(s[2 * np2],     a, b0, b2);
                mma_fp8(s[2 * np2 + 1], a, b1, b3);
            }
        }

#pragma unroll
        for (int jj = 0; jj < 4; jj++) {
            float e00 = __expf(s[jj][0] * 0.015625f);
            float e01 = __expf(s[jj][1] * 0.015625f);
            float e10 = __expf(s[jj][2] * 0.015625f);
            float e11 = __expf(s[jj][3] * 0.015625f);
            l0 += e00 + e01;
            l1 += e10 + e11;
            sts16(pst0 + jj * 8, pack_e4m3x2(e00, e01));
            sts16(pst1 + jj * 8, pack_e4m3x2(e10, e11));
        }
        __syncthreads();

        const uint32_t vtb = sb + VTOFF + cur * VTSZ + (uint32_t)(w * 32) * 80 + vldL;
        const uint32_t plb = sb + POFF + pldL;
#pragma unroll
        for (int kc2 = 0; kc2 < 2; kc2++) {
            uint32_t pa[4][4];
#pragma unroll
            for (int mg = 0; mg < 4; mg++)
                ldmx4(pa[mg][0], pa[mg][1], pa[mg][2], pa[mg][3],
                      plb + (uint32_t)(mg * 16 * 80 + kc2 * 32));
#pragma unroll
            for (int np2 = 0; np2 < 2; np2++) {
                uint32_t v0, v1, v2, v3;
                ldmx4(v0, v1, v2, v3, vtb + (uint32_t)(np2 * 16 * 80 + kc2 * 32));
#pragma unroll
                for (int mg = 0; mg < 4; mg++) {
                    mma_fp8(o[mg][2 * np2],     pa[mg], v0, v1);
                    mma_fp8(o[mg][2 * np2 + 1], pa[mg], v2, v3);
                }
            }
        }

        if (kt + 1 < 64) cp_wait<0>();
        __syncthreads();
    }

    l0 += __shfl_xor_sync(0xffffffffu, l0, 1);
    l0 += __shfl_xor_sync(0xffffffffu, l0, 2);
    l1 += __shfl_xor_sync(0xffffffffu, l1, 1);
    l1 += __shfl_xor_sync(0xffffffffu, l1, 2);
    float* sLf = (float*)(smem + LOFF);     // [2][64]
    if ((lane & 3) == 0) {
        sLf[h * 64 + prow0] = l0;
        sLf[h * 64 + prow1] = l1;
    }
    __syncthreads();

    const float gamma8 = __ldg(gamma_p) * 0.125f;
    const size_t rowbase = (size_t)batch * NTOK + mt * 64;
#pragma unroll
    for (int mg = 0; mg < 4; mg++) {
        int r0 = mg * 16 + (lane >> 2);
        float gl0 = gamma8 / (sLf[r0] + sLf[64 + r0]);
        float gl1 = gamma8 / (sLf[r0 + 8] + sLf[64 + r0 + 8]);
        const float* x0 = g_x + (rowbase + r0) * FDIM;
        const float* x1 = x0 + 8 * FDIM;
        float* o0 = out + (rowbase + r0) * FDIM;
        float* o1 = o0 + 8 * FDIM;
#pragma unroll
        for (int nt = 0; nt < 4; nt++) {
            int col = w * 32 + nt * 8 + (lane & 3) * 2;
            float2 xa = *(const float2*)&x0[col];
            float2 xb = *(const float2*)&x1[col];
            float2 va, vb;
            va.x = o[mg][nt][0] * gl0 + xa.x;
            va.y = o[mg][nt][1] * gl0 + xa.y;
            vb.x = o[mg][nt][2] * gl1 + xb.x;
            vb.y = o[mg][nt][3] * gl1 + xb.y;
            *(float2*)&o0[col] = va;
            *(float2*)&o1[col] = vb;
        }
    }
}

// ---------------- launch ----------------------------------------------------------
extern "C" void kernel_launch(void* const* d_in, const int* in_sizes, int n_in,
                              void* d_out, int out_size) {
    (void)in_sizes; (void)n_in; (void)out_size;
    const float* inputs = (const float*)d_in[0];
    const float* W_proj = (const float*)d_in[1];
    const float* b_proj = (const float*)d_in[2];
    const float* W_q    = (const float*)d_in[3];
    const float* b_q    = (const float*)d_in[4];
    const float* W_k    = (const float*)d_in[5];
    const float* b_k    = (const float*)d_in[6];
    const float* W_v    = (const float*)d_in[7];
    const float* b_v    = (const float*)d_in[8];
    const float* gamma  = (const float*)d_in[9];
    float* out = (float*)d_out;

    cudaFuncSetAttribute(attn_kernel, cudaFuncAttributeMaxDynamicSharedMemorySize,
                         ATT_SMEM);

    // 4 launches; attn stays at capture slot (abs idx 3)
    prep_kernel<<<2099, 256>>>(inputs, W_proj, b_proj, W_q, b_q, W_k, b_k, W_v, b_v);
    wsplit_kernel<<<128, 256>>>(W_proj);
    qkv_kernel<<<dim3(MTOT / 128, 16), 256>>>(b_proj);
    attn_kernel<<<dim3(NTOK / 64, BATCH), 256, ATT_SMEM>>>(out, gamma);
}

// round 16
// speedup vs baseline: 1.0491x; 1.0491x over previous
#include <cuda_runtime.h>
#include <cuda_bf16.h>
#include <cstdint>

#define BATCH 4
#define NTOK  4096
#define CIN   128
#define FDIM  256
#define MTOT  (BATCH*NTOK)   // 16384

// ---------------- scratch (device globals) -----------------------------------
__device__ float          g_x  [MTOT*FDIM];   // fp32 x for residual
__device__ __nv_bfloat16  g_ib [MTOT*CIN];    // bf16 hi(inputs)
__device__ __nv_bfloat16  g_ibl[MTOT*CIN];    // bf16 lo(inputs)
__device__ __nv_bfloat16  g_wc [CIN*3*FDIM];  // folded weights [128][768]
__device__ float          g_bc [3*FDIM];      // folded biases
__device__ __nv_bfloat16  g_wph[CIN*FDIM];    // hi(W_proj)
__device__ __nv_bfloat16  g_wpl[CIN*FDIM];    // lo(W_proj)
__device__ unsigned char  g_q8 [MTOT*FDIM];   // Q in e4m3, scaled x8
__device__ unsigned char  g_k8 [MTOT*FDIM];   // K in e4m3, scaled x8
// V e4m3 x8, transposed tile-major: [batch][ktile=64][d=256][key_in_tile=64]
__device__ unsigned char  g_v8t[MTOT*FDIM];

// ---------------- helpers ------------------------------------------------------
static __device__ __forceinline__ uint32_t smem_u32(const void* p) {
    return (uint32_t)__cvta_generic_to_shared(p);
}
static __device__ __forceinline__ void ldmx4(uint32_t& r0, uint32_t& r1,
                                             uint32_t& r2, uint32_t& r3, uint32_t addr) {
    asm volatile("ldmatrix.sync.aligned.m8n8.x4.shared.b16 {%0,%1,%2,%3}, [%4];"
                 : "=r"(r0), "=r"(r1), "=r"(r2), "=r"(r3) : "r"(addr));
}
static __device__ __forceinline__ void ldmx4t(uint32_t& r0, uint32_t& r1,
                                              uint32_t& r2, uint32_t& r3, uint32_t addr) {
    asm volatile("ldmatrix.sync.aligned.m8n8.x4.trans.shared.b16 {%0,%1,%2,%3}, [%4];"
                 : "=r"(r0), "=r"(r1), "=r"(r2), "=r"(r3) : "r"(addr));
}
static __device__ __forceinline__ void mma_bf16(float* c, const uint32_t* a,
                                                uint32_t b0, uint32_t b1) {
    asm volatile("mma.sync.aligned.m16n8k16.row.col.f32.bf16.bf16.f32 "
                 "{%0,%1,%2,%3}, {%4,%5,%6,%7}, {%8,%9}, {%0,%1,%2,%3};"
                 : "+f"(c[0]), "+f"(c[1]), "+f"(c[2]), "+f"(c[3])
                 : "r"(a[0]), "r"(a[1]), "r"(a[2]), "r"(a[3]), "r"(b0), "r"(b1));
}
static __device__ __forceinline__ void mma_fp8(float* c, const uint32_t* a,
                                               uint32_t b0, uint32_t b1) {
    asm volatile("mma.sync.aligned.m16n8k32.row.col.f32.e4m3.e4m3.f32 "
                 "{%0,%1,%2,%3}, {%4,%5,%6,%7}, {%8,%9}, {%0,%1,%2,%3};"
                 : "+f"(c[0]), "+f"(c[1]), "+f"(c[2]), "+f"(c[3])
                 : "r"(a[0]), "r"(a[1]), "r"(a[2]), "r"(a[3]), "r"(b0), "r"(b1));
}
static __device__ __forceinline__ unsigned short pack_e4m3x2(float lo, float hi) {
    unsigned short d;
    asm("cvt.rn.satfinite.e4m3x2.f32 %0, %1, %2;" : "=h"(d) : "f"(hi), "f"(lo));
    return d;
}
static __device__ __forceinline__ float ex2f(float x) {
    float r;
    asm("ex2.approx.f32 %0, %1;" : "=f"(r) : "f"(x));
    return r;
}
static __device__ __forceinline__ void sts16(uint32_t addr, unsigned short v) {
    asm volatile("st.shared.b16 [%0], %1;" :: "r"(addr), "h"(v));
}
static __device__ __forceinline__ void cp16(uint32_t s, const void* g) {
    asm volatile("cp.async.cg.shared.global [%0], [%1], 16;" :: "r"(s), "l"(g));
}
static __device__ __forceinline__ void cp_commit() {
    asm volatile("cp.async.commit_group;");
}
template<int N> static __device__ __forceinline__ void cp_wait() {
    asm volatile("cp.async.wait_group %0;" :: "n"(N));
}

// ---------------- kernel 0: prep = conv(hi+lo) + fold + bias_fold ---------------
__global__ void __launch_bounds__(256) prep_kernel(const float* __restrict__ in,
                                                   const float* __restrict__ Wp,
                                                   const float* __restrict__ bp,
                                                   const float* __restrict__ Wq,
                                                   const float* __restrict__ bq,
                                                   const float* __restrict__ Wk,
                                                   const float* __restrict__ bk,
                                                   const float* __restrict__ Wv,
                                                   const float* __restrict__ bv) {
    __shared__ float sWj[64][65];
    __shared__ float sWp[64][36];
    const int bx = blockIdx.x, tid = threadIdx.x;

    if (bx < 2048) {                       // ---- conv: fp32 -> bf16 hi + lo ----
        int i = bx * 256 + tid;
        float4 v = ((const float4*)in)[i];
        __nv_bfloat16 hx = __float2bfloat16(v.x);
        __nv_bfloat16 hy = __float2bfloat16(v.y);
        __nv_bfloat16 hz = __float2bfloat16(v.z);
        __nv_bfloat16 hw = __float2bfloat16(v.w);
        ((__nv_bfloat162*)g_ib)[2 * i]     = __nv_bfloat162(hx, hy);
        ((__nv_bfloat162*)g_ib)[2 * i + 1] = __nv_bfloat162(hz, hw);
        ((__nv_bfloat162*)g_ibl)[2 * i] = __floats2bfloat162_rn(
            v.x - __bfloat162float(hx), v.y - __bfloat162float(hy));
        ((__nv_bfloat162*)g_ibl)[2 * i + 1] = __floats2bfloat162_rn(
            v.z - __bfloat162float(hz), v.w - __bfloat162float(hw));
        return;
    }
    if (bx < 2096) {                       // ---- fold Wc = Wp @ W{q,k,v} ----
        const int f = bx - 2048;
        const int j = f >> 4;
        const int g0 = ((f >> 2) & 3) * 64, c0 = (f & 3) * 32;
        const float* Wj = (j == 0) ? Wq : ((j == 1) ? Wk : Wv);
        const int tg = tid & 63, tc = tid >> 6;
        float acc[8];
#pragma unroll
        for (int i = 0; i < 8; i++) acc[i] = 0.f;

        for (int f0 = 0; f0 < 256; f0 += 64) {
#pragma unroll
            for (int i = tid; i < 4096; i += 256)
                sWj[i >> 6][i & 63] = Wj[(size_t)(f0 + (i >> 6)) * 256 + g0 + (i & 63)];
#pragma unroll
            for (int i = tid; i < 2048; i += 256)
                sWp[i & 63][i >> 6] = Wp[(size_t)(c0 + (i >> 6)) * 256 + f0 + (i & 63)];
            __syncthreads();
#pragma unroll 16
            for (int ff = 0; ff < 64; ff++) {
                float wj = sWj[ff][tg];
                float4 p0 = *(const float4*)&sWp[ff][tc * 8];
                float4 p1 = *(const float4*)&sWp[ff][tc * 8 + 4];
                acc[0] += p0.x * wj; acc[1] += p0.y * wj;
                acc[2] += p0.z * wj; acc[3] += p0.w * wj;
                acc[4] += p1.x * wj; acc[5] += p1.y * wj;
                acc[6] += p1.z * wj; acc[7] += p1.w * wj;
            }
            __syncthreads();
        }
#pragma unroll
        for (int i = 0; i < 8; i++)
            g_wc[(size_t)(c0 + tc * 8 + i) * 768 + j * 256 + g0 + tg] =
                __float2bfloat16(acc[i]);
        return;
    }
    {                                      // ---- bias fold ----
        const int j = bx - 2096, g = tid;
        const float* Wj = (j == 0) ? Wq : ((j == 1) ? Wk : Wv);
        const float* bj = (j == 0) ? bq : ((j == 1) ? bk : bv);
        float acc = bj[g];
        for (int f = 0; f < 256; f++) acc += bp[f] * Wj[(size_t)f * 256 + g];
        g_bc[j * 256 + g] = acc;
    }
}

// ---------------- kernel 0b: split W_proj into hi/lo bf16 -----------------------
__global__ void __launch_bounds__(256) wsplit_kernel(const float* __restrict__ Wp) {
    int i = blockIdx.x * 256 + threadIdx.x;   // 32768 elems, grid 128
    float w = Wp[i];
    __nv_bfloat16 h = __float2bfloat16(w);
    g_wph[i] = h;
    g_wpl[i] = __float2bfloat16(w - __bfloat162float(h));
}

// ---------------- kernel 2: Q/K/V (fp8) + x (split-bf16 fp32), BM=128 -----------
// Grid (128, 16), 256 threads (8 warps x 16 rows). y<12: q/k/v. y>=12: x-path.
__global__ void __launch_bounds__(256) qkv_kernel(const float* __restrict__ bp) {
    __shared__ __align__(16) __nv_bfloat16 sA[128][72];   // 18 KB
    __shared__ __align__(16) __nv_bfloat16 sW[64][72];    // 9 KB
    __shared__ __align__(16) unsigned char sT[64 * 144];  // V transpose staging (9 KB)
    const int m0 = blockIdx.x * 128;
    const int tid = threadIdx.x, warp = tid >> 5, lane = tid & 31;

    float o[8][4];
#pragma unroll
    for (int jj = 0; jj < 8; jj++)
#pragma unroll
        for (int r = 0; r < 4; r++) o[jj][r] = 0.f;

    const uint32_t a_addr0 = smem_u32(&sA[warp * 16 + (lane & 15)][(lane & 16) >> 1]);
    const uint32_t b_addr0 = smem_u32(&sW[(lane & 7) + (lane & 8)][(lane & 16) >> 1]);
    const int g = lane >> 2, qd = lane & 3;

    if (blockIdx.y < 12) {
        // ---------------- q/k/v path ----------------
        const int j = blockIdx.y >> 2, g0 = (blockIdx.y & 3) * 64;

        for (int k0 = 0; k0 < CIN; k0 += 64) {
            __syncthreads();
#pragma unroll
            for (int i = tid; i < 1024; i += 256) {     // A: 128x64 bf16
                int r = i >> 3, c8 = i & 7;
                *(uint4*)&sA[r][c8 * 8] =
                    *(const uint4*)&g_ib[(size_t)(m0 + r) * CIN + k0 + c8 * 8];
            }
#pragma unroll
            for (int i = tid; i < 512; i += 256) {      // W: 64x64 bf16
                int r = i >> 3, c8 = i & 7;
                *(uint4*)&sW[r][c8 * 8] =
                    *(const uint4*)&g_wc[(size_t)(k0 + r) * 768 + j * 256 + g0 + c8 * 8];
            }
            __syncthreads();
#pragma unroll
            for (int kc = 0; kc < 4; kc++) {
                uint32_t a[4];
                ldmx4(a[0], a[1], a[2], a[3], a_addr0 + kc * 16 * 2);
#pragma unroll
                for (int np = 0; np < 4; np++) {
                    uint32_t b0, b1, b2, b3;
                    ldmx4t(b0, b1, b2, b3,
                           b_addr0 + (uint32_t)(kc * 16 * 72 + np * 16) * 2);
                    mma_bf16(o[2 * np],     a, b0, b1);
                    mma_bf16(o[2 * np + 1], a, b2, b3);
                }
            }
        }
        const int row = m0 + warp * 16 + g;
        if (j < 2) {
            unsigned char* out8 = (j == 0) ? g_q8 : g_k8;
#pragma unroll
            for (int jj = 0; jj < 8; jj++) {
                int col = g0 + jj * 8 + qd * 2;
                float bf0 = g_bc[j * 256 + col], bf1 = g_bc[j * 256 + col + 1];
                *(unsigned short*)&out8[(size_t)row * FDIM + col] =
                    pack_e4m3x2((o[jj][0] + bf0) * 8.f, (o[jj][1] + bf1) * 8.f);
                *(unsigned short*)&out8[(size_t)(row + 8) * FDIM + col] =
                    pack_e4m3x2((o[jj][2] + bf0) * 8.f, (o[jj][3] + bf1) * 8.f);
            }
        } else {
            // V: transpose to [d][token(128)] in smem (e4m3 x8), 2 ktiles/block
            const int batch = m0 >> 12;
            const int kt0 = (m0 & 4095) >> 6;          // first of 2 tiles
            const int t0 = warp * 16 + g, t1 = t0 + 8; // token-in-block 0..127
#pragma unroll
            for (int jj = 0; jj < 8; jj++) {
                int c = jj * 8 + qd * 2;  // local d index 0..63
                float bf0 = g_bc[512 + g0 + c], bf1 = g_bc[512 + g0 + c + 1];
                sT[c * 144 + t0]       = (unsigned char)pack_e4m3x2((o[jj][0] + bf0) * 8.f, 0.f);
                sT[(c + 1) * 144 + t0] = (unsigned char)pack_e4m3x2((o[jj][1] + bf1) * 8.f, 0.f);
                sT[c * 144 + t1]       = (unsigned char)pack_e4m3x2((o[jj][2] + bf0) * 8.f, 0.f);
                sT[(c + 1) * 144 + t1] = (unsigned char)pack_e4m3x2((o[jj][3] + bf1) * 8.f, 0.f);
            }
            __syncthreads();
            if (tid < 128) {
                const int til = tid >> 6, c = tid & 63;
                unsigned char* dst =
                    g_v8t + (((size_t)(batch * 64 + kt0 + til) * 256) + g0 + c) * 64;
                const uint4* src = (const uint4*)&sT[c * 144 + til * 64];
                ((uint4*)dst)[0] = src[0];
                ((uint4*)dst)[1] = src[1];
                ((uint4*)dst)[2] = src[2];
                ((uint4*)dst)[3] = src[3];
            }
        }
    } else {
        // ---------------- x-path: x = hi@Whi + hi@Wlo + lo@Whi + bp ----------------
        const int g0 = (blockIdx.y - 12) * 64;

#pragma unroll 1
        for (int c = 0; c < 6; c++) {
            const int pass = c >> 1, ksub = (c & 1) * 64;
            const __nv_bfloat16* Asrc = (pass == 2) ? g_ibl : g_ib;
            const __nv_bfloat16* Wsrc = (pass == 1) ? g_wpl : g_wph;
            __syncthreads();
#pragma unroll
            for (int i = tid; i < 1024; i += 256) {
                int r = i >> 3, c8 = i & 7;
                *(uint4*)&sA[r][c8 * 8] =
                    *(const uint4*)&Asrc[(size_t)(m0 + r) * CIN + ksub + c8 * 8];
            }
#pragma unroll
            for (int i = tid; i < 512; i += 256) {
                int r = i >> 3, c8 = i & 7;
                *(uint4*)&sW[r][c8 * 8] =
                    *(const uint4*)&Wsrc[(size_t)(ksub + r) * FDIM + g0 + c8 * 8];
            }
            __syncthreads();
#pragma unroll
            for (int kc = 0; kc < 4; kc++) {
                uint32_t a[4];
                ldmx4(a[0], a[1], a[2], a[3], a_addr0 + kc * 16 * 2);
#pragma unroll
                for (int np = 0; np < 4; np++) {
                    uint32_t b0, b1, b2, b3;
                    ldmx4t(b0, b1, b2, b3,
                           b_addr0 + (uint32_t)(kc * 16 * 72 + np * 16) * 2);
                    mma_bf16(o[2 * np],     a, b0, b1);
                    mma_bf16(o[2 * np + 1], a, b2, b3);
                }
            }
        }
        const int row = m0 + warp * 16 + g;
#pragma unroll
        for (int jj = 0; jj < 8; jj++) {
            int col = g0 + jj * 8 + qd * 2;
            float b0 = bp[col], b1 = bp[col + 1];
            float2 v0 = make_float2(o[jj][0] + b0, o[jj][1] + b1);
            float2 v1 = make_float2(o[jj][2] + b0, o[jj][3] + b1);
            *(float2*)&g_x[(size_t)row * FDIM + col] = v0;
            *(float2*)&g_x[(size_t)(row + 8) * FDIM + col] = v1;
        }
    }
}

// ---------------- kernel 3: all-fp8 flash attention ------------------------------
// Grid (64,4); 256 threads (8 warps). BM=64, BN=64, D=256, 2 CTAs/SM.
// r14 core + ex2-folded softmax + iter-63 epilogue x-prefetch into dead smem.
#define QOFF  0
#define KOFF  16384
#define VTOFF 49152
#define VTSZ  20480
#define POFF  90112
#define LOFF  95232
#define ATT_SMEM (LOFF + 512)
// log2(e)/64
#define EXPC  0.02254243f

__global__ void __launch_bounds__(256, 2) attn_kernel(float* __restrict__ out,
                                                      const float* __restrict__ gamma_p) {
    extern __shared__ char smem[];
    const uint32_t sb = smem_u32(smem);
    const int batch = blockIdx.y, mt = blockIdx.x;
    const int tid = threadIdx.x, w = tid >> 5, lane = tid & 31;
    const int rg = w >> 1;
    const int h  = w & 1;
    const int rlow = (lane & 7) + (lane & 8);
    const int ghi  = (lane >> 4) & 1;
    const int l7   = lane & 7;

    const unsigned char* Qg  = g_q8  + ((size_t)batch * NTOK + mt * 64) * FDIM;
    const unsigned char* Kg  = g_k8  + (size_t)batch * NTOK * FDIM;
    const unsigned char* VTg = g_v8t + (size_t)batch * 64 * 16384;

    // loop-invariant prefetch bases
    const int pr = tid >> 4, pg = tid & 15;
    const uint32_t kS0 = (uint32_t)(pr * 256 + ((pg ^ (pr & 7)) << 4));
    const uint32_t kG0 = (uint32_t)(pr * 256 + pg * 16);
    const int pd = tid >> 2, p4 = tid & 3;
    const uint32_t vS0 = (uint32_t)(pd * 80 + p4 * 16);
    const uint32_t vG0 = (uint32_t)(pd * 64 + p4 * 16);

    // ---- prologue: Q, K0, Vt0 in one group ----
#pragma unroll
    for (int c = 0; c < 4; c++) {
        cp16(sb + QOFF + kS0 + c * 4096, Qg + kG0 + c * 4096);
        cp16(sb + KOFF + kS0 + c * 4096, Kg + kG0 + c * 4096);
        cp16(sb + VTOFF + vS0 + c * 5120, VTg + vG0 + c * 4096);
    }
    cp_commit();

    // persistent prefetch pointers (measured win, round 14)
    const unsigned char* Kp = Kg + 16384;
    const unsigned char* Vp = VTg + 16384;

    float o[4][4][4];
#pragma unroll
    for (int mg = 0; mg < 4; mg++)
#pragma unroll
        for (int nt = 0; nt < 4; nt++)
#pragma unroll
            for (int r = 0; r < 4; r++) o[mg][nt][r] = 0.f;
    float l0 = 0.f, l1 = 0.f;

    const uint32_t e16 = (uint32_t)((ghi ^ l7) << 4);
    const uint32_t qbase = sb + QOFF + (rg * 16 + rlow) * 256;
    const int prow0 = rg * 16 + (lane >> 2), prow1 = prow0 + 8;
    const uint32_t pst0 = sb + POFF + prow0 * 80 + h * 32 + (lane & 3) * 2;
    const uint32_t pst1 = sb + POFF + prow1 * 80 + h * 32 + (lane & 3) * 2;
    const uint32_t pldL = (uint32_t)(((l7 + ((lane >> 3) & 1) * 8) * 80) + ghi * 16);
    const uint32_t vldL = (uint32_t)(((l7 + ghi * 8) * 80) + (((lane >> 3) & 1) * 16));

    cp_wait<0>();
    __syncthreads();

    for (int kt = 0; kt < 64; kt++) {
        const int cur = kt & 1;

        if (kt + 1 < 64) {
            const uint32_t kb = sb + KOFF  + (cur ^ 1) * 16384;
            const uint32_t vb = sb + VTOFF + (cur ^ 1) * VTSZ;
            cp16(kb + kS0,         Kp + kG0);
            cp16(kb + kS0 + 4096,  Kp + kG0 + 4096);
            cp16(kb + kS0 + 8192,  Kp + kG0 + 8192);
            cp16(kb + kS0 + 12288, Kp + kG0 + 12288);
            cp16(vb + vS0,         Vp + vG0);
            cp16(vb + vS0 + 5120,  Vp + vG0 + 4096);
            cp16(vb + vS0 + 10240, Vp + vG0 + 8192);
            cp16(vb + vS0 + 15360, Vp + vG0 + 12288);
            cp_commit();
            Kp += 16384;
            Vp += 16384;
        }

        float s[4][4];
#pragma unroll
        for (int jj = 0; jj < 4; jj++)
#pragma unroll
            for (int r = 0; r < 4; r++) s[jj][r] = 0.f;

        const uint32_t kb = sb + KOFF + cur * 16384 + (uint32_t)((h * 32 + rlow) * 256);
#pragma unroll
        for (int kc = 0; kc < 8; kc++) {
            const uint32_t gsw = ((uint32_t)(kc * 32)) ^ e16;
            uint32_t a[4];
            ldmx4(a[0], a[1], a[2], a[3], qbase + gsw);
#pragma unroll
            for (int np2 = 0; np2 < 2; np2++) {
                uint32_t b0, b1, b2, b3;
                ldmx4(b0, b1, b2, b3, kb + (uint32_t)(np2 * 4096) + gsw);
                mma_fp8(s[2 * np2],     a, b0, b2);
                mma_fp8(s[2 * np2 + 1], a, b1, b3);
            }
        }

        // no-max softmax: P = exp(S/64) = ex2(S * log2e/64)
#pragma unroll
        for (int jj = 0; jj < 4; jj++) {
            float e00 = ex2f(s[jj][0] * EXPC);
            float e01 = ex2f(s[jj][1] * EXPC);
            float e10 = ex2f(s[jj][2] * EXPC);
            float e11 = ex2f(s[jj][3] * EXPC);
            l0 += e00 + e01;
            l1 += e10 + e11;
            sts16(pst0 + jj * 8, pack_e4m3x2(e00, e01));
            sts16(pst1 + jj * 8, pack_e4m3x2(e10, e11));
        }
        __syncthreads();   // P visible; all warps done with S (Q/K dead at kt=63)

        // iter 63: prefetch this CTA's x slab (64 KB) into dead Q/K0/K1/Vt0 smem
        if (kt == 63) {
            const char* Xg = (const char*)(g_x + ((size_t)batch * NTOK + mt * 64) * FDIM);
#pragma unroll
            for (int c = 0; c < 16; c++) {
                const uint32_t off = (uint32_t)((c * 256 + tid) * 16);
                cp16(sb + off, Xg + off);
            }
            cp_commit();
        }

        const uint32_t vtb = sb + VTOFF + cur * VTSZ + (uint32_t)(w * 32) * 80 + vldL;
        const uint32_t plb = sb + POFF + pldL;
#pragma unroll
        for (int kc2 = 0; kc2 < 2; kc2++) {
            uint32_t pa[4][4];
#pragma unroll
            for (int mg = 0; mg < 4; mg++)
                ldmx4(pa[mg][0], pa[mg][1], pa[mg][2], pa[mg][3],
                      plb + (uint32_t)(mg * 16 * 80 + kc2 * 32));
#pragma unroll
            for (int np2 = 0; np2 < 2; np2++) {
                uint32_t v0, v1, v2, v3;
                ldmx4(v0, v1, v2, v3, vtb + (uint32_t)(np2 * 16 * 80 + kc2 * 32));
#pragma unroll
                for (int mg = 0; mg < 4; mg++) {
                    mma_fp8(o[mg][2 * np2],     pa[mg], v0, v1);
                    mma_fp8(o[mg][2 * np2 + 1], pa[mg], v2, v3);
                }
            }
        }

        cp_wait<0>();      // drains K/Vt prefetch (kt<63) or x prefetch (kt=63)
        __syncthreads();
    }

    l0 += __shfl_xor_sync(0xffffffffu, l0, 1);
    l0 += __shfl_xor_sync(0xffffffffu, l0, 2);
    l1 += __shfl_xor_sync(0xffffffffu, l1, 1);
    l1 += __shfl_xor_sync(0xffffffffu, l1, 2);
    float* sLf = (float*)(smem + LOFF);     // [2][64]
    if ((lane & 3) == 0) {
        sLf[h * 64 + prow0] = l0;
        sLf[h * 64 + prow1] = l1;
    }
    __syncthreads();

    const float gamma8 = __ldg(gamma_p) * 0.125f;
    const size_t rowbase = (size_t)batch * NTOK + mt * 64;
#pragma unroll
    for (int mg = 0; mg < 4; mg++) {
        int r0 = mg * 16 + (lane >> 2);
        float gl0 = gamma8 / (sLf[r0] + sLf[64 + r0]);
        float gl1 = gamma8 / (sLf[r0 + 8] + sLf[64 + r0 + 8]);
        const char* xs0 = smem + r0 * 1024;       // x row r0 in smem
        const char* xs1 = xs0 + 8 * 1024;
        float* o0 = out + (rowbase + r0) * FDIM;
        float* o1 = o0 + 8 * FDIM;
#pragma unroll
        for (int nt = 0; nt < 4; nt++) {
            int col = w * 32 + nt * 8 + (lane & 3) * 2;
            float2 xa = *(const float2*)(xs0 + col * 4);
            float2 xb = *(const float2*)(xs1 + col * 4);
            float2 va, vb;
            va.x = o[mg][nt][0] * gl0 + xa.x;
            va.y = o[mg][nt][1] * gl0 + xa.y;
            vb.x = o[mg][nt][2] * gl1 + xb.x;
            vb.y = o[mg][nt][3] * gl1 + xb.y;
            *(float2*)&o0[col] = va;
            *(float2*)&o1[col] = vb;
        }
    }
}

// ---------------- launch ----------------------------------------------------------
extern "C" void kernel_launch(void* const* d_in, const int* in_sizes, int n_in,
                              void* d_out, int out_size) {
    (void)in_sizes; (void)n_in; (void)out_size;
    const float* inputs = (const float*)d_in[0];
    const float* W_proj = (const float*)d_in[1];
    const float* b_proj = (const float*)d_in[2];
    const float* W_q    = (const float*)d_in[3];
    const float* b_q    = (const float*)d_in[4];
    const float* W_k    = (const float*)d_in[5];
    const float* b_k    = (const float*)d_in[6];
    const float* W_v    = (const float*)d_in[7];
    const float* b_v    = (const float*)d_in[8];
    const float* gamma  = (const float*)d_in[9];
    float* out = (float*)d_out;

    cudaFuncSetAttribute(attn_kernel, cudaFuncAttributeMaxDynamicSharedMemorySize,
                         ATT_SMEM);

    // 4 launches; attn stays at capture slot (abs idx 3)
    prep_kernel<<<2099, 256>>>(inputs, W_proj, b_proj, W_q, b_q, W_k, b_k, W_v, b_v);
    wsplit_kernel<<<128, 256>>>(W_proj);
    qkv_kernel<<<dim3(MTOT / 128, 16), 256>>>(b_proj);
    attn_kernel<<<dim3(NTOK / 64, BATCH), 256, ATT_SMEM>>>(out, gamma);
}

// round 17
// speedup vs baseline: 1.0704x; 1.0203x over previous
#include <cuda_runtime.h>
#include <cuda_bf16.h>
#include <cuda_fp16.h>
#include <cstdint>

#define BATCH 4
#define NTOK  4096
#define CIN   128
#define FDIM  256
#define MTOT  (BATCH*NTOK)   // 16384

// ---------------- scratch (device globals) -----------------------------------
__device__ float          g_x  [MTOT*FDIM];   // fp32 x for residual
__device__ __nv_bfloat16  g_ib [MTOT*CIN];    // bf16 hi(inputs) (qkv path)
__device__ __half         g_ih [MTOT*CIN];    // fp16(inputs)    (x path)
__device__ __nv_bfloat16  g_wc [CIN*3*FDIM];  // folded weights [128][768]
__device__ float          g_bc [3*FDIM];      // folded biases
__device__ __half         g_wph[CIN*FDIM];    // fp16 hi(W_proj)
__device__ __half         g_wpl[CIN*FDIM];    // fp16 lo(W_proj)
__device__ unsigned char  g_q8 [MTOT*FDIM];   // Q in e4m3, scaled x8
__device__ unsigned char  g_k8 [MTOT*FDIM];   // K in e4m3, scaled x8
// V e4m3 x8, transposed tile-major: [batch][ktile=64][d=256][key_in_tile=64]
__device__ unsigned char  g_v8t[MTOT*FDIM];

// ---------------- helpers ------------------------------------------------------
static __device__ __forceinline__ uint32_t smem_u32(const void* p) {
    return (uint32_t)__cvta_generic_to_shared(p);
}
static __device__ __forceinline__ void ldmx4(uint32_t& r0, uint32_t& r1,
                                             uint32_t& r2, uint32_t& r3, uint32_t addr) {
    asm volatile("ldmatrix.sync.aligned.m8n8.x4.shared.b16 {%0,%1,%2,%3}, [%4];"
                 : "=r"(r0), "=r"(r1), "=r"(r2), "=r"(r3) : "r"(addr));
}
static __device__ __forceinline__ void ldmx4t(uint32_t& r0, uint32_t& r1,
                                              uint32_t& r2, uint32_t& r3, uint32_t addr) {
    asm volatile("ldmatrix.sync.aligned.m8n8.x4.trans.shared.b16 {%0,%1,%2,%3}, [%4];"
                 : "=r"(r0), "=r"(r1), "=r"(r2), "=r"(r3) : "r"(addr));
}
static __device__ __forceinline__ void mma_bf16(float* c, const uint32_t* a,
                                                uint32_t b0, uint32_t b1) {
    asm volatile("mma.sync.aligned.m16n8k16.row.col.f32.bf16.bf16.f32 "
                 "{%0,%1,%2,%3}, {%4,%5,%6,%7}, {%8,%9}, {%0,%1,%2,%3};"
                 : "+f"(c[0]), "+f"(c[1]), "+f"(c[2]), "+f"(c[3])
                 : "r"(a[0]), "r"(a[1]), "r"(a[2]), "r"(a[3]), "r"(b0), "r"(b1));
}
static __device__ __forceinline__ void mma_f16(float* c, const uint32_t* a,
                                               uint32_t b0, uint32_t b1) {
    asm volatile("mma.sync.aligned.m16n8k16.row.col.f32.f16.f16.f32 "
                 "{%0,%1,%2,%3}, {%4,%5,%6,%7}, {%8,%9}, {%0,%1,%2,%3};"
                 : "+f"(c[0]), "+f"(c[1]), "+f"(c[2]), "+f"(c[3])
                 : "r"(a[0]), "r"(a[1]), "r"(a[2]), "r"(a[3]), "r"(b0), "r"(b1));
}
static __device__ __forceinline__ void mma_fp8(float* c, const uint32_t* a,
                                               uint32_t b0, uint32_t b1) {
    asm volatile("mma.sync.aligned.m16n8k32.row.col.f32.e4m3.e4m3.f32 "
                 "{%0,%1,%2,%3}, {%4,%5,%6,%7}, {%8,%9}, {%0,%1,%2,%3};"
                 : "+f"(c[0]), "+f"(c[1]), "+f"(c[2]), "+f"(c[3])
                 : "r"(a[0]), "r"(a[1]), "r"(a[2]), "r"(a[3]), "r"(b0), "r"(b1));
}
static __device__ __forceinline__ unsigned short pack_e4m3x2(float lo, float hi) {
    unsigned short d;
    asm("cvt.rn.satfinite.e4m3x2.f32 %0, %1, %2;" : "=h"(d) : "f"(hi), "f"(lo));
    return d;
}
static __device__ __forceinline__ float ex2f(float x) {
    float r;
    asm("ex2.approx.f32 %0, %1;" : "=f"(r) : "f"(x));
    return r;
}
static __device__ __forceinline__ void sts16(uint32_t addr, unsigned short v) {
    asm volatile("st.shared.b16 [%0], %1;" :: "r"(addr), "h"(v));
}
static __device__ __forceinline__ void cp16(uint32_t s, const void* g) {
    asm volatile("cp.async.cg.shared.global [%0], [%1], 16;" :: "r"(s), "l"(g));
}
static __device__ __forceinline__ void cp_commit() {
    asm volatile("cp.async.commit_group;");
}
template<int N> static __device__ __forceinline__ void cp_wait() {
    asm volatile("cp.async.wait_group %0;" :: "n"(N));
}

// ---------------- kernel 0: prep = conv(bf16 + fp16) + fold + bias_fold ---------
__global__ void __launch_bounds__(256) prep_kernel(const float* __restrict__ in,
                                                   const float* __restrict__ Wp,
                                                   const float* __restrict__ bp,
                                                   const float* __restrict__ Wq,
                                                   const float* __restrict__ bq,
                                                   const float* __restrict__ Wk,
                                                   const float* __restrict__ bk,
                                                   const float* __restrict__ Wv,
                                                   const float* __restrict__ bv) {
    __shared__ float sWj[64][65];
    __shared__ float sWp[64][36];
    const int bx = blockIdx.x, tid = threadIdx.x;

    if (bx < 2048) {                       // ---- conv: fp32 -> bf16 + fp16 ----
        int i = bx * 256 + tid;
        float4 v = ((const float4*)in)[i];
        ((__nv_bfloat162*)g_ib)[2 * i]     = __floats2bfloat162_rn(v.x, v.y);
        ((__nv_bfloat162*)g_ib)[2 * i + 1] = __floats2bfloat162_rn(v.z, v.w);
        ((__half2*)g_ih)[2 * i]     = __floats2half2_rn(v.x, v.y);
        ((__half2*)g_ih)[2 * i + 1] = __floats2half2_rn(v.z, v.w);
        return;
    }
    if (bx < 2096) {                       // ---- fold Wc = Wp @ W{q,k,v} ----
        const int f = bx - 2048;
        const int j = f >> 4;
        const int g0 = ((f >> 2) & 3) * 64, c0 = (f & 3) * 32;
        const float* Wj = (j == 0) ? Wq : ((j == 1) ? Wk : Wv);
        const int tg = tid & 63, tc = tid >> 6;
        float acc[8];
#pragma unroll
        for (int i = 0; i < 8; i++) acc[i] = 0.f;

        for (int f0 = 0; f0 < 256; f0 += 64) {
#pragma unroll
            for (int i = tid; i < 4096; i += 256)
                sWj[i >> 6][i & 63] = Wj[(size_t)(f0 + (i >> 6)) * 256 + g0 + (i & 63)];
#pragma unroll
            for (int i = tid; i < 2048; i += 256)
                sWp[i & 63][i >> 6] = Wp[(size_t)(c0 + (i >> 6)) * 256 + f0 + (i & 63)];
            __syncthreads();
#pragma unroll 16
            for (int ff = 0; ff < 64; ff++) {
                float wj = sWj[ff][tg];
                float4 p0 = *(const float4*)&sWp[ff][tc * 8];
                float4 p1 = *(const float4*)&sWp[ff][tc * 8 + 4];
                acc[0] += p0.x * wj; acc[1] += p0.y * wj;
                acc[2] += p0.z * wj; acc[3] += p0.w * wj;
                acc[4] += p1.x * wj; acc[5] += p1.y * wj;
                acc[6] += p1.z * wj; acc[7] += p1.w * wj;
            }
            __syncthreads();
        }
#pragma unroll
        for (int i = 0; i < 8; i++)
            g_wc[(size_t)(c0 + tc * 8 + i) * 768 + j * 256 + g0 + tg] =
                __float2bfloat16(acc[i]);
        return;
    }
    {                                      // ---- bias fold ----
        const int j = bx - 2096, g = tid;
        const float* Wj = (j == 0) ? Wq : ((j == 1) ? Wk : Wv);
        const float* bj = (j == 0) ? bq : ((j == 1) ? bk : bv);
        float acc = bj[g];
        for (int f = 0; f < 256; f++) acc += bp[f] * Wj[(size_t)f * 256 + g];
        g_bc[j * 256 + g] = acc;
    }
}

// ---------------- kernel 0b: split W_proj into fp16 hi/lo -----------------------
__global__ void __launch_bounds__(256) wsplit_kernel(const float* __restrict__ Wp) {
    int i = blockIdx.x * 256 + threadIdx.x;   // 32768 elems, grid 128
    float w = Wp[i];
    __half h = __float2half_rn(w);
    g_wph[i] = h;
    g_wpl[i] = __float2half_rn(w - __half2float(h));
}

// ---------------- kernel 2: Q/K/V (fp8) + x (split-fp16 fp32), BM=128 -----------
// Grid (128, 16), 256 threads (8 warps x 16 rows). y<12: q/k/v. y>=12: x-path.
__global__ void __launch_bounds__(256) qkv_kernel(const float* __restrict__ bp) {
    __shared__ __align__(16) __nv_bfloat16 sA[128][72];   // 18 KB (also fp16 tiles)
    __shared__ __align__(16) __nv_bfloat16 sW[64][72];    // 9 KB
    __shared__ __align__(16) unsigned char sT[64 * 144];  // V transpose staging (9 KB)
    const int m0 = blockIdx.x * 128;
    const int tid = threadIdx.x, warp = tid >> 5, lane = tid & 31;

    float o[8][4];
#pragma unroll
    for (int jj = 0; jj < 8; jj++)
#pragma unroll
        for (int r = 0; r < 4; r++) o[jj][r] = 0.f;

    const uint32_t a_addr0 = smem_u32(&sA[warp * 16 + (lane & 15)][(lane & 16) >> 1]);
    const uint32_t b_addr0 = smem_u32(&sW[(lane & 7) + (lane & 8)][(lane & 16) >> 1]);
    const int g = lane >> 2, qd = lane & 3;

    if (blockIdx.y < 12) {
        // ---------------- q/k/v path (bf16) ----------------
        const int j = blockIdx.y >> 2, g0 = (blockIdx.y & 3) * 64;

        for (int k0 = 0; k0 < CIN; k0 += 64) {
            __syncthreads();
#pragma unroll
            for (int i = tid; i < 1024; i += 256) {     // A: 128x64 bf16
                int r = i >> 3, c8 = i & 7;
                *(uint4*)&sA[r][c8 * 8] =
                    *(const uint4*)&g_ib[(size_t)(m0 + r) * CIN + k0 + c8 * 8];
            }
#pragma unroll
            for (int i = tid; i < 512; i += 256) {      // W: 64x64 bf16
                int r = i >> 3, c8 = i & 7;
                *(uint4*)&sW[r][c8 * 8] =
                    *(const uint4*)&g_wc[(size_t)(k0 + r) * 768 + j * 256 + g0 + c8 * 8];
            }
            __syncthreads();
#pragma unroll
            for (int kc = 0; kc < 4; kc++) {
                uint32_t a[4];
                ldmx4(a[0], a[1], a[2], a[3], a_addr0 + kc * 16 * 2);
#pragma unroll
                for (int np = 0; np < 4; np++) {
                    uint32_t b0, b1, b2, b3;
                    ldmx4t(b0, b1, b2, b3,
                           b_addr0 + (uint32_t)(kc * 16 * 72 + np * 16) * 2);
                    mma_bf16(o[2 * np],     a, b0, b1);
                    mma_bf16(o[2 * np + 1], a, b2, b3);
                }
            }
        }
        const int row = m0 + warp * 16 + g;
        if (j < 2) {
            unsigned char* out8 = (j == 0) ? g_q8 : g_k8;
#pragma unroll
            for (int jj = 0; jj < 8; jj++) {
                int col = g0 + jj * 8 + qd * 2;
                float bf0 = g_bc[j * 256 + col], bf1 = g_bc[j * 256 + col + 1];
                *(unsigned short*)&out8[(size_t)row * FDIM + col] =
                    pack_e4m3x2((o[jj][0] + bf0) * 8.f, (o[jj][1] + bf1) * 8.f);
                *(unsigned short*)&out8[(size_t)(row + 8) * FDIM + col] =
                    pack_e4m3x2((o[jj][2] + bf0) * 8.f, (o[jj][3] + bf1) * 8.f);
            }
        } else {
            // V: transpose to [d][token(128)] in smem (e4m3 x8), 2 ktiles/block
            const int batch = m0 >> 12;
            const int kt0 = (m0 & 4095) >> 6;          // first of 2 tiles
            const int t0 = warp * 16 + g, t1 = t0 + 8; // token-in-block 0..127
#pragma unroll
            for (int jj = 0; jj < 8; jj++) {
                int c = jj * 8 + qd * 2;  // local d index 0..63
                float bf0 = g_bc[512 + g0 + c], bf1 = g_bc[512 + g0 + c + 1];
                sT[c * 144 + t0]       = (unsigned char)pack_e4m3x2((o[jj][0] + bf0) * 8.f, 0.f);
                sT[(c + 1) * 144 + t0] = (unsigned char)pack_e4m3x2((o[jj][1] + bf1) * 8.f, 0.f);
                sT[c * 144 + t1]       = (unsigned char)pack_e4m3x2((o[jj][2] + bf0) * 8.f, 0.f);
                sT[(c + 1) * 144 + t1] = (unsigned char)pack_e4m3x2((o[jj][3] + bf1) * 8.f, 0.f);
            }
            __syncthreads();
            if (tid < 128) {
                const int til = tid >> 6, c = tid & 63;
                unsigned char* dst =
                    g_v8t + (((size_t)(batch * 64 + kt0 + til) * 256) + g0 + c) * 64;
                const uint4* src = (const uint4*)&sT[c * 144 + til * 64];
                ((uint4*)dst)[0] = src[0];
                ((uint4*)dst)[1] = src[1];
                ((uint4*)dst)[2] = src[2];
                ((uint4*)dst)[3] = src[3];
            }
        }
    } else {
        // ------------- x-path (fp16): x = h16@Wh16 + h16@Wl16 + bp -------------
        const int g0 = (blockIdx.y - 12) * 64;

#pragma unroll 1
        for (int c = 0; c < 4; c++) {
            const int pass = c >> 1, ksub = (c & 1) * 64;
            const __half* Wsrc = (pass == 0) ? g_wph : g_wpl;
            __syncthreads();
#pragma unroll
            for (int i = tid; i < 1024; i += 256) {
                int r = i >> 3, c8 = i & 7;
                *(uint4*)&sA[r][c8 * 8] =
                    *(const uint4*)&g_ih[(size_t)(m0 + r) * CIN + ksub + c8 * 8];
            }
#pragma unroll
            for (int i = tid; i < 512; i += 256) {
                int r = i >> 3, c8 = i & 7;
                *(uint4*)&sW[r][c8 * 8] =
                    *(const uint4*)&Wsrc[(size_t)(ksub + r) * FDIM + g0 + c8 * 8];
            }
            __syncthreads();
#pragma unroll
            for (int kc = 0; kc < 4; kc++) {
                uint32_t a[4];
                ldmx4(a[0], a[1], a[2], a[3], a_addr0 + kc * 16 * 2);
#pragma unroll
                for (int np = 0; np < 4; np++) {
                    uint32_t b0, b1, b2, b3;
                    ldmx4t(b0, b1, b2, b3,
                           b_addr0 + (uint32_t)(kc * 16 * 72 + np * 16) * 2);
                    mma_f16(o[2 * np],     a, b0, b1);
                    mma_f16(o[2 * np + 1], a, b2, b3);
                }
            }
        }
        const int row = m0 + warp * 16 + g;
#pragma unroll
        for (int jj = 0; jj < 8; jj++) {
            int col = g0 + jj * 8 + qd * 2;
            float b0 = bp[col], b1 = bp[col + 1];
            float2 v0 = make_float2(o[jj][0] + b0, o[jj][1] + b1);
            float2 v1 = make_float2(o[jj][2] + b0, o[jj][3] + b1);
            *(float2*)&g_x[(size_t)row * FDIM + col] = v0;
            *(float2*)&g_x[(size_t)(row + 8) * FDIM + col] = v1;
        }
    }
}

// ---------------- kernel 3: all-fp8 flash attention (round-16 winner) ------------
// Grid (64,4); 256 threads (8 warps). BM=64, BN=64, D=256, 2 CTAs/SM.
#define QOFF  0
#define KOFF  16384
#define VTOFF 49152
#define VTSZ  20480
#define POFF  90112
#define LOFF  95232
#define ATT_SMEM (LOFF + 512)
// log2(e)/64
#define EXPC  0.02254243f

__global__ void __launch_bounds__(256, 2) attn_kernel(float* __restrict__ out,
                                                      const float* __restrict__ gamma_p) {
    extern __shared__ char smem[];
    const uint32_t sb = smem_u32(smem);
    const int batch = blockIdx.y, mt = blockIdx.x;
    const int tid = threadIdx.x, w = tid >> 5, lane = tid & 31;
    const int rg = w >> 1;
    const int h  = w & 1;
    const int rlow = (lane & 7) + (lane & 8);
    const int ghi  = (lane >> 4) & 1;
    const int l7   = lane & 7;

    const unsigned char* Qg  = g_q8  + ((size_t)batch * NTOK + mt * 64) * FDIM;
    const unsigned char* Kg  = g_k8  + (size_t)batch * NTOK * FDIM;
    const unsigned char* VTg = g_v8t + (size_t)batch * 64 * 16384;

    // loop-invariant prefetch bases
    const int pr = tid >> 4, pg = tid & 15;
    const uint32_t kS0 = (uint32_t)(pr * 256 + ((pg ^ (pr & 7)) << 4));
    const uint32_t kG0 = (uint32_t)(pr * 256 + pg * 16);
    const int pd = tid >> 2, p4 = tid & 3;
    const uint32_t vS0 = (uint32_t)(pd * 80 + p4 * 16);
    const uint32_t vG0 = (uint32_t)(pd * 64 + p4 * 16);

    // ---- prologue: Q, K0, Vt0 in one group ----
#pragma unroll
    for (int c = 0; c < 4; c++) {
        cp16(sb + QOFF + kS0 + c * 4096, Qg + kG0 + c * 4096);
        cp16(sb + KOFF + kS0 + c * 4096, Kg + kG0 + c * 4096);
        cp16(sb + VTOFF + vS0 + c * 5120, VTg + vG0 + c * 4096);
    }
    cp_commit();

    const unsigned char* Kp = Kg + 16384;
    const unsigned char* Vp = VTg + 16384;

    float o[4][4][4];
#pragma unroll
    for (int mg = 0; mg < 4; mg++)
#pragma unroll
        for (int nt = 0; nt < 4; nt++)
#pragma unroll
            for (int r = 0; r < 4; r++) o[mg][nt][r] = 0.f;
    float l0 = 0.f, l1 = 0.f;

    const uint32_t e16 = (uint32_t)((ghi ^ l7) << 4);
    const uint32_t qbase = sb + QOFF + (rg * 16 + rlow) * 256;
    const int prow0 = rg * 16 + (lane >> 2), prow1 = prow0 + 8;
    const uint32_t pst0 = sb + POFF + prow0 * 80 + h * 32 + (lane & 3) * 2;
    const uint32_t pst1 = sb + POFF + prow1 * 80 + h * 32 + (lane & 3) * 2;
    const uint32_t pldL = (uint32_t)(((l7 + ((lane >> 3) & 1) * 8) * 80) + ghi * 16);
    const uint32_t vldL = (uint32_t)(((l7 + ghi * 8) * 80) + (((lane >> 3) & 1) * 16));

    cp_wait<0>();
    __syncthreads();

    for (int kt = 0; kt < 64; kt++) {
        const int cur = kt & 1;

        if (kt + 1 < 64) {
            const uint32_t kb = sb + KOFF  + (cur ^ 1) * 16384;
            const uint32_t vb = sb + VTOFF + (cur ^ 1) * VTSZ;
            cp16(kb + kS0,         Kp + kG0);
            cp16(kb + kS0 + 4096,  Kp + kG0 + 4096);
            cp16(kb + kS0 + 8192,  Kp + kG0 + 8192);
            cp16(kb + kS0 + 12288, Kp + kG0 + 12288);
            cp16(vb + vS0,         Vp + vG0);
            cp16(vb + vS0 + 5120,  Vp + vG0 + 4096);
            cp16(vb + vS0 + 10240, Vp + vG0 + 8192);
            cp16(vb + vS0 + 15360, Vp + vG0 + 12288);
            cp_commit();
            Kp += 16384;
            Vp += 16384;
        }

        float s[4][4];
#pragma unroll
        for (int jj = 0; jj < 4; jj++)
#pragma unroll
            for (int r = 0; r < 4; r++) s[jj][r] = 0.f;

        const uint32_t kb = sb + KOFF + cur * 16384 + (uint32_t)((h * 32 + rlow) * 256);
#pragma unroll
        for (int kc = 0; kc < 8; kc++) {
            const uint32_t gsw = ((uint32_t)(kc * 32)) ^ e16;
            uint32_t a[4];
            ldmx4(a[0], a[1], a[2], a[3], qbase + gsw);
#pragma unroll
            for (int np2 = 0; np2 < 2; np2++) {
                uint32_t b0, b1, b2, b3;
                ldmx4(b0, b1, b2, b3, kb + (uint32_t)(np2 * 4096) + gsw);
                mma_fp8(s[2 * np2],     a, b0, b2);
                mma_fp8(s[2 * np2 + 1], a, b1, b3);
            }
        }

        // no-max softmax: P = exp(S/64) = ex2(S * log2e/64)
#pragma unroll
        for (int jj = 0; jj < 4; jj++) {
            float e00 = ex2f(s[jj][0] * EXPC);
            float e01 = ex2f(s[jj][1] * EXPC);
            float e10 = ex2f(s[jj][2] * EXPC);
            float e11 = ex2f(s[jj][3] * EXPC);
            l0 += e00 + e01;
            l1 += e10 + e11;
            sts16(pst0 + jj * 8, pack_e4m3x2(e00, e01));
            sts16(pst1 + jj * 8, pack_e4m3x2(e10, e11));
        }
        __syncthreads();   // P visible; all warps done with S (Q/K dead at kt=63)

        // iter 63: prefetch this CTA's x slab (64 KB) into dead Q/K0/K1/Vt0 smem
        if (kt == 63) {
            const char* Xg = (const char*)(g_x + ((size_t)batch * NTOK + mt * 64) * FDIM);
#pragma unroll
            for (int c = 0; c < 16; c++) {
                const uint32_t off = (uint32_t)((c * 256 + tid) * 16);
                cp16(sb + off, Xg + off);
            }
            cp_commit();
        }

        const uint32_t vtb = sb + VTOFF + cur * VTSZ + (uint32_t)(w * 32) * 80 + vldL;
        const uint32_t plb = sb + POFF + pldL;
#pragma unroll
        for (int kc2 = 0; kc2 < 2; kc2++) {
            uint32_t pa[4][4];
#pragma unroll
            for (int mg = 0; mg < 4; mg++)
                ldmx4(pa[mg][0], pa[mg][1], pa[mg][2], pa[mg][3],
                      plb + (uint32_t)(mg * 16 * 80 + kc2 * 32));
#pragma unroll
            for (int np2 = 0; np2 < 2; np2++) {
                uint32_t v0, v1, v2, v3;
                ldmx4(v0, v1, v2, v3, vtb + (uint32_t)(np2 * 16 * 80 + kc2 * 32));
#pragma unroll
                for (int mg = 0; mg < 4; mg++) {
                    mma_fp8(o[mg][2 * np2],     pa[mg], v0, v1);
                    mma_fp8(o[mg][2 * np2 + 1], pa[mg], v2, v3);
                }
            }
        }

        cp_wait<0>();      // drains K/Vt prefetch (kt<63) or x prefetch (kt=63)
        __syncthreads();
    }

    l0 += __shfl_xor_sync(0xffffffffu, l0, 1);
    l0 += __shfl_xor_sync(0xffffffffu, l0, 2);
    l1 += __shfl_xor_sync(0xffffffffu, l1, 1);
    l1 += __shfl_xor_sync(0xffffffffu, l1, 2);
    float* sLf = (float*)(smem + LOFF);     // [2][64]
    if ((lane & 3) == 0) {
        sLf[h * 64 + prow0] = l0;
        sLf[h * 64 + prow1] = l1;
    }
    __syncthreads();

    const float gamma8 = __ldg(gamma_p) * 0.125f;
    const size_t rowbase = (size_t)batch * NTOK + mt * 64;
#pragma unroll
    for (int mg = 0; mg < 4; mg++) {
        int r0 = mg * 16 + (lane >> 2);
        float gl0 = gamma8 / (sLf[r0] + sLf[64 + r0]);
        float gl1 = gamma8 / (sLf[r0 + 8] + sLf[64 + r0 + 8]);
        const char* xs0 = smem + r0 * 1024;       // x row r0 in smem
        const char* xs1 = xs0 + 8 * 1024;
        float* o0 = out + (rowbase + r0) * FDIM;
        float* o1 = o0 + 8 * FDIM;
#pragma unroll
        for (int nt = 0; nt < 4; nt++) {
            int col = w * 32 + nt * 8 + (lane & 3) * 2;
            float2 xa = *(const float2*)(xs0 + col * 4);
            float2 xb = *(const float2*)(xs1 + col * 4);
            float2 va, vb;
            va.x = o[mg][nt][0] * gl0 + xa.x;
            va.y = o[mg][nt][1] * gl0 + xa.y;
            vb.x = o[mg][nt][2] * gl1 + xb.x;
            vb.y = o[mg][nt][3] * gl1 + xb.y;
            *(float2*)&o0[col] = va;
            *(float2*)&o1[col] = vb;
        }
    }
}

// ---------------- launch ----------------------------------------------------------
extern "C" void kernel_launch(void* const* d_in, const int* in_sizes, int n_in,
                              void* d_out, int out_size) {
    (void)in_sizes; (void)n_in; (void)out_size;
    const float* inputs = (const float*)d_in[0];
    const float* W_proj = (const float*)d_in[1];
    const float* b_proj = (const float*)d_in[2];
    const float* W_q    = (const float*)d_in[3];
    const float* b_q    = (const float*)d_in[4];
    const float* W_k    = (const float*)d_in[5];
    const float* b_k    = (const float*)d_in[6];
    const float* W_v    = (const float*)d_in[7];
    const float* b_v    = (const float*)d_in[8];
    const float* gamma  = (const float*)d_in[9];
    float* out = (float*)d_out;

    cudaFuncSetAttribute(attn_kernel, cudaFuncAttributeMaxDynamicSharedMemorySize,
                         ATT_SMEM);

    // 4 launches; attn stays at capture slot (abs idx 3)
    prep_kernel<<<2099, 256>>>(inputs, W_proj, b_proj, W_q, b_q, W_k, b_k, W_v, b_v);
    wsplit_kernel<<<128, 256>>>(W_proj);
    qkv_kernel<<<dim3(MTOT / 128, 16), 256>>>(b_proj);
    attn_kernel<<<dim3(NTOK / 64, BATCH), 256, ATT_SMEM>>>(out, gamma);
}